// round 12
// baseline (speedup 1.0000x reference)
#include <cuda_runtime.h>
#include <cuda_bf16.h>
#include <cstdint>
#include <math.h>

#define TOK   200704
#define CDIM  384
#define NHEAD 12
#define DHEAD 32
#define NWIN  4096
#define NPOS  49
#define HID   1536

// ---------------- static scratch ----------------------------------------------
__device__ __nv_bfloat16 g_xw [(size_t)TOK * CDIM];
__device__ __nv_bfloat16 g_qkv[(size_t)TOK * 3 * CDIM];
__device__ __nv_bfloat16 g_att[(size_t)TOK * CDIM];
__device__ float         g_x2 [(size_t)TOK * CDIM];
__device__ __nv_bfloat16 g_xn2[(size_t)TOK * CDIM];
__device__ __nv_bfloat16 g_h1 [(size_t)TOK * HID];
__device__ __nv_bfloat16 g_wqkv [CDIM * 3 * CDIM];
__device__ __nv_bfloat16 g_wproj[CDIM * CDIM];
__device__ __nv_bfloat16 g_wm1  [CDIM * HID];
__device__ __nv_bfloat16 g_wm2  [HID * CDIM];

// ---------------- helpers -------------------------------------------------------
__device__ __forceinline__ uint32_t smem_u32(const void* p) {
    uint32_t a;
    asm("{ .reg .u64 t; cvta.to.shared.u64 t, %1; cvt.u32.u64 %0, t; }" : "=r"(a) : "l"(p));
    return a;
}
__device__ __forceinline__ void cp16(uint32_t dst, const void* src) {
    asm volatile("cp.async.cg.shared.global [%0], [%1], 16;" :: "r"(dst), "l"(src));
}
#define CP_COMMIT() asm volatile("cp.async.commit_group;" ::: "memory")
#define CP_WAIT(n)  asm volatile("cp.async.wait_group %0;" :: "n"(n) : "memory")

__device__ __forceinline__ void ldsm4(uint32_t* r, uint32_t addr) {
    asm volatile("ldmatrix.sync.aligned.m8n8.x4.shared.b16 {%0,%1,%2,%3}, [%4];"
                 : "=r"(r[0]), "=r"(r[1]), "=r"(r[2]), "=r"(r[3]) : "r"(addr));
}
__device__ __forceinline__ void ldsm4t(uint32_t* r, uint32_t addr) {
    asm volatile("ldmatrix.sync.aligned.m8n8.x4.trans.shared.b16 {%0,%1,%2,%3}, [%4];"
                 : "=r"(r[0]), "=r"(r[1]), "=r"(r[2]), "=r"(r[3]) : "r"(addr));
}
__device__ __forceinline__ void mma_bf16(float* c, const uint32_t* a, const uint32_t* b) {
    asm volatile("mma.sync.aligned.m16n8k16.row.col.f32.bf16.bf16.f32 "
                 "{%0,%1,%2,%3}, {%4,%5,%6,%7}, {%8,%9}, {%0,%1,%2,%3};"
                 : "+f"(c[0]), "+f"(c[1]), "+f"(c[2]), "+f"(c[3])
                 : "r"(a[0]), "r"(a[1]), "r"(a[2]), "r"(a[3]), "r"(b[0]), "r"(b[1]));
}
__device__ __forceinline__ uint32_t cvt_bf2(float lo, float hi) {
    uint32_t r;
    asm("cvt.rn.satfinite.bf16x2.f32 %0, %1, %2;" : "=r"(r) : "f"(hi), "f"(lo));
    return r;
}

// ---------------- fused weight convert ------------------------------------------
#define WS0 (CDIM * 3 * CDIM)
#define WS1 (CDIM * CDIM)
#define WS2 (CDIM * HID)
#define WS3 (HID * CDIM)
__global__ void wconv_all(const float* __restrict__ w0, const float* __restrict__ w1,
                          const float* __restrict__ w2, const float* __restrict__ w3,
                          __nv_bfloat16* __restrict__ d0, __nv_bfloat16* __restrict__ d1,
                          __nv_bfloat16* __restrict__ d2, __nv_bfloat16* __restrict__ d3) {
    int i = blockIdx.x * 256 + threadIdx.x;
    if (i < WS0) { d0[i] = __float2bfloat16(w0[i]); return; }
    i -= WS0;
    if (i < WS1) { d1[i] = __float2bfloat16(w1[i]); return; }
    i -= WS1;
    if (i < WS2) { d2[i] = __float2bfloat16(w2[i]); return; }
    i -= WS2;
    if (i < WS3) { d3[i] = __float2bfloat16(w3[i]); }
}

// ---------------- LayerNorm: warp-per-token, float4, shuffle-only reduce --------
template <bool REMAP>
__global__ void __launch_bounds__(256)
ln_kernel(const float* __restrict__ xin,
          const float* __restrict__ sc,
          const float* __restrict__ bi,
          __nv_bfloat16* __restrict__ xout) {
    int t = blockIdx.x * 8 + (threadIdx.x >> 5);
    int lane = threadIdx.x & 31;
    size_t src;
    if (REMAP) {
        int win = t / NPOS, npos = t - win * NPOS;
        int b = win >> 6, wy = (win >> 3) & 7, wx = win & 7;
        int py = npos / 7, px = npos - py * 7;
        int sy = wy * 7 + py + 3; if (sy >= 56) sy -= 56;
        int sx = wx * 7 + px + 3; if (sx >= 56) sx -= 56;
        src = (size_t)b * 3136 + sy * 56 + sx;
    } else src = (size_t)t;

    const float4* xp = (const float4*)(xin + src * CDIM);
    float4 v[3];
    float s = 0.f, s2 = 0.f;
#pragma unroll
    for (int i = 0; i < 3; ++i) {
        v[i] = xp[lane + 32 * i];
        s  += v[i].x + v[i].y + v[i].z + v[i].w;
        s2 += v[i].x * v[i].x + v[i].y * v[i].y + v[i].z * v[i].z + v[i].w * v[i].w;
    }
#pragma unroll
    for (int o = 16; o > 0; o >>= 1) {
        s  += __shfl_xor_sync(0xffffffffu, s,  o);
        s2 += __shfl_xor_sync(0xffffffffu, s2, o);
    }
    float mu  = s * (1.0f / CDIM);
    float var = s2 * (1.0f / CDIM) - mu * mu;
    float r = rsqrtf(var + 1e-6f);

    __nv_bfloat16* op = xout + (size_t)t * CDIM;
#pragma unroll
    for (int i = 0; i < 3; ++i) {
        int idx = (lane + 32 * i) * 4;
        float4 g = *(const float4*)(sc + idx);
        float4 b4 = *(const float4*)(bi + idx);
        float o0 = (v[i].x - mu) * r * g.x + b4.x;
        float o1 = (v[i].y - mu) * r * g.y + b4.y;
        float o2 = (v[i].z - mu) * r * g.z + b4.z;
        float o3 = (v[i].w - mu) * r * g.w + b4.w;
        uint2 pk;
        pk.x = cvt_bf2(o0, o1);
        pk.y = cvt_bf2(o2, o3);
        *(uint2*)(op + idx) = pk;
    }
}

// ---------------- HMMA windowed attention: Q,K direct-LDG, V smem only ----------
__global__ void __launch_bounds__(32, 24)
attn_mma(const __nv_bfloat16* __restrict__ qkv, __nv_bfloat16* __restrict__ out) {
    int blk = blockIdx.x;
    int win = blk / NHEAD, head = blk - win * NHEAD;
    int wy = (win >> 3) & 7, wx = win & 7;

    __shared__ __align__(16) __nv_bfloat16 Vs[64 * 40];
    __shared__ int rg[64];

    const int lane = threadIdx.x;
    const __nv_bfloat16* base  = qkv + (size_t)win * NPOS * (3 * CDIM);
    const __nv_bfloat16* qhead = base + head * DHEAD;
    const __nv_bfloat16* khead = base + CDIM + head * DHEAD;

    // zero V pad rows 49..63
#pragma unroll
    for (int i = lane; i < 15 * 20; i += 32) {
        int r = 49 + i / 20, c = i % 20;
        ((float*)Vs)[r * 20 + c] = 0.f;
    }
    for (int u = lane; u < 196; u += 32) {
        int r = u >> 2, cc = u & 3;
        const __nv_bfloat16* rp = base + (size_t)r * (3 * CDIM) + head * DHEAD + cc * 8;
        *(uint4*)(Vs + r * 40 + cc * 8) = *(const uint4*)(rp + 2 * CDIM);
    }
    for (int p = lane; p < NPOS; p += 32) {
        int py = p / 7, px = p - py * 7;
        int hy = wy * 7 + py, hx = wx * 7 + px;
        int cy = hy < 49 ? 0 : (hy < 53 ? 1 : 2);
        int cx = hx < 49 ? 0 : (hx < 53 ? 1 : 2);
        rg[p] = cy * 3 + cx;
    }
    __syncwarp();

    const uint32_t vb = smem_u32(Vs);
    const float scale = 0.17677669529663687f;

    // per-lane K-column masks (frag n-index = lane>>2 within each 8-wide tile)
    int  rk[7][2];
    bool kv_ok[7][2];
#pragma unroll
    for (int nt = 0; nt < 7; ++nt)
#pragma unroll
        for (int c = 0; c < 2; ++c) {
            int k = 8 * nt + 2 * (lane & 3) + c;
            kv_ok[nt][c] = (k < 49);
            rk[nt][c] = rg[k < 49 ? k : 0];
        }

    // K frag row/ok (mt-invariant addressing)
    const int kfr = lane >> 2;                 // n within tile
    const int kfc = (lane & 3) * 2;            // k pair base

    for (int mt = 0; mt < 4; ++mt) {
        // ---- Q A-frags directly from global (predicated; pad rows -> 0) ----
        int r0 = mt * 16 + (lane >> 2), r1 = r0 + 8;
        bool ok0 = r0 < NPOS, ok1 = r1 < NPOS;
        const __nv_bfloat16* q0p = qhead + (size_t)r0 * (3 * CDIM);
        const __nv_bfloat16* q1p = qhead + (size_t)r1 * (3 * CDIM);
        uint32_t afr[2][4];
#pragma unroll
        for (int kk = 0; kk < 2; ++kk) {
            int c0 = kk * 16 + (lane & 3) * 2, c1 = c0 + 8;
            afr[kk][0] = ok0 ? *(const uint32_t*)(q0p + c0) : 0u;
            afr[kk][1] = ok1 ? *(const uint32_t*)(q1p + c0) : 0u;
            afr[kk][2] = ok0 ? *(const uint32_t*)(q0p + c1) : 0u;
            afr[kk][3] = ok1 ? *(const uint32_t*)(q1p + c1) : 0u;
        }

        float sc[7][4];
#pragma unroll
        for (int nt = 0; nt < 7; ++nt)
#pragma unroll
            for (int r = 0; r < 4; ++r) sc[nt][r] = 0.f;

        // ---- S += Q K^T, K B-frags direct from global (L1-resident) ----
#pragma unroll
        for (int kk = 0; kk < 2; ++kk) {
#pragma unroll
            for (int nt = 0; nt < 7; ++nt) {
                int krow = 8 * nt + kfr;
                bool kok = krow < NPOS;
                const __nv_bfloat16* kp =
                    khead + (size_t)krow * (3 * CDIM) + kk * 16 + kfc;
                uint32_t bfr[2];
                bfr[0] = kok ? *(const uint32_t*)(kp)     : 0u;
                bfr[1] = kok ? *(const uint32_t*)(kp + 8) : 0u;
                mma_bf16(sc[nt], afr[kk], bfr);
            }
        }

        // ---- mask + softmax ----
        int rq0 = ok0 ? rg[r0] : -1;
        int rq1 = ok1 ? rg[r1] : -1;
        float mx0 = -1e30f, mx1 = -1e30f;
#pragma unroll
        for (int nt = 0; nt < 7; ++nt) {
#pragma unroll
            for (int r = 0; r < 4; ++r) {
                int half = r >> 1, c = r & 1;
                float s = sc[nt][r] * scale;
                if (!kv_ok[nt][c]) s = -1e30f;
                else if (rk[nt][c] != (half ? rq1 : rq0)) s -= 100.f;
                sc[nt][r] = s;
                if (half == 0) mx0 = fmaxf(mx0, s); else mx1 = fmaxf(mx1, s);
            }
        }
        mx0 = fmaxf(mx0, __shfl_xor_sync(~0u, mx0, 1));
        mx0 = fmaxf(mx0, __shfl_xor_sync(~0u, mx0, 2));
        mx1 = fmaxf(mx1, __shfl_xor_sync(~0u, mx1, 1));
        mx1 = fmaxf(mx1, __shfl_xor_sync(~0u, mx1, 2));
        float s0 = 0.f, s1 = 0.f;
#pragma unroll
        for (int nt = 0; nt < 7; ++nt) {
            float e0 = __expf(sc[nt][0] - mx0); sc[nt][0] = e0; s0 += e0;
            float e1 = __expf(sc[nt][1] - mx0); sc[nt][1] = e1; s0 += e1;
            float e2 = __expf(sc[nt][2] - mx1); sc[nt][2] = e2; s1 += e2;
            float e3 = __expf(sc[nt][3] - mx1); sc[nt][3] = e3; s1 += e3;
        }
        s0 += __shfl_xor_sync(~0u, s0, 1); s0 += __shfl_xor_sync(~0u, s0, 2);
        s1 += __shfl_xor_sync(~0u, s1, 1); s1 += __shfl_xor_sync(~0u, s1, 2);
        float inv0 = 1.f / s0, inv1 = 1.f / s1;

        // ---- O_mt = P_mt V ----
        float acc[4][4];
#pragma unroll
        for (int nt = 0; nt < 4; ++nt)
#pragma unroll
            for (int r = 0; r < 4; ++r) acc[nt][r] = 0.f;

#pragma unroll
        for (int kt = 0; kt < 4; ++kt) {
            uint32_t vbf[4][2];
#pragma unroll
            for (int np = 0; np < 2; ++np) {
                uint32_t t[4];
                ldsm4t(t, vb + (kt * 16 + (lane & 15)) * 80 + ((lane >> 4) * 8 + np * 16) * 2);
                vbf[2 * np][0] = t[0]; vbf[2 * np][1] = t[1];
                vbf[2 * np + 1][0] = t[2]; vbf[2 * np + 1][1] = t[3];
            }
            uint32_t a[4];
            const int ta = 2 * kt, tb = 2 * kt + 1;
            a[0] = cvt_bf2(sc[ta][0], sc[ta][1]);
            a[1] = cvt_bf2(sc[ta][2], sc[ta][3]);
            if (tb < 7) {
                a[2] = cvt_bf2(sc[tb][0], sc[tb][1]);
                a[3] = cvt_bf2(sc[tb][2], sc[tb][3]);
            } else { a[2] = 0u; a[3] = 0u; }
#pragma unroll
            for (int nt = 0; nt < 4; ++nt) mma_bf16(acc[nt], a, vbf[nt]);
        }

#pragma unroll
        for (int half = 0; half < 2; ++half) {
            int q = r0 + 8 * half;
            if (q < NPOS) {
                __nv_bfloat16* op = out + ((size_t)win * NPOS + q) * CDIM + head * DHEAD;
                float iv = half ? inv1 : inv0;
#pragma unroll
                for (int nt = 0; nt < 4; ++nt) {
                    int d = nt * 8 + 2 * (lane & 3);
                    *(__nv_bfloat162*)(op + d) = __floats2bfloat162_rn(
                        acc[nt][2 * half] * iv, acc[nt][2 * half + 1] * iv);
                }
            }
        }
    }
}

// ---------------- HMMA bf16 GEMM (measured-best: 128x128, BK=64, 2 CTA/SM) ------
__device__ __forceinline__ float gelu_tanh(float v) {
    float u = 0.7978845608028654f * (v + 0.044715f * v * v * v);
    return 0.5f * v * (1.0f + tanhf(u));
}

#define ASTG 18432u
#define BSTG 17408u
#define SMEM_GEMM (2u * (ASTG + BSTG))

template <int EPI>
__global__ __launch_bounds__(256, 2)
void hgemm(const __nv_bfloat16* __restrict__ A,
           const __nv_bfloat16* __restrict__ Bw,
           const float* __restrict__ bias,
           void* __restrict__ CoutV,
           const float* __restrict__ res,
           int Nn, int K) {
    extern __shared__ char smraw[];
    const uint32_t a_base = smem_u32(smraw);
    const uint32_t b_base = a_base + 2u * ASTG;

    const int tid = threadIdx.x, lane = tid & 31, warp = tid >> 5;
    const int wm = warp & 3, wn = warp >> 2;
    const int bx = blockIdx.x, by = blockIdx.y;

    const __nv_bfloat16* Ag = A  + (size_t)(by * 128) * K;
    const __nv_bfloat16* Bg = Bw + bx * 128;

    auto load_stage = [&](int buf, int k0) {
        uint32_t a_s = a_base + buf * ASTG;
        uint32_t b_s = b_base + buf * BSTG;
#pragma unroll
        for (int j = 0; j < 4; ++j) {
            int id = tid + j * 256;
            int row = id >> 3, cc = id & 7;
            cp16(a_s + row * 144 + cc * 16, Ag + (size_t)row * K + k0 + cc * 8);
        }
#pragma unroll
        for (int j = 0; j < 4; ++j) {
            int id = tid + j * 256;
            int row = id >> 4, cc = id & 15;
            cp16(b_s + row * 272 + cc * 16, Bg + (size_t)(k0 + row) * Nn + cc * 8);
        }
        CP_COMMIT();
    };

    float acc[2][8][4];
#pragma unroll
    for (int i = 0; i < 2; ++i)
#pragma unroll
        for (int j = 0; j < 8; ++j)
#pragma unroll
            for (int q = 0; q < 4; ++q) acc[i][j][q] = 0.f;

    const int kIters = K >> 6;
    load_stage(0, 0);

    const uint32_t a_lm = a_base + (wm * 32 + (lane & 15)) * 144 + (lane >> 4) * 16;
    const uint32_t b_lm = b_base + (lane & 15) * 272 + (wn * 64 + (lane >> 4) * 8) * 2;

    for (int i = 0; i < kIters; ++i) {
        int cur = i & 1;
        if (i + 1 < kIters) { load_stage(1 - cur, (i + 1) * 64); CP_WAIT(1); }
        else CP_WAIT(0);
        __syncthreads();

        uint32_t aS = a_lm + cur * ASTG;
        uint32_t bS = b_lm + cur * BSTG;
#pragma unroll
        for (int kk = 0; kk < 4; ++kk) {
            uint32_t a[2][4];
#pragma unroll
            for (int mi = 0; mi < 2; ++mi)
                ldsm4(a[mi], aS + mi * 16 * 144 + kk * 32);
            uint32_t b[8][2];
#pragma unroll
            for (int nq = 0; nq < 4; ++nq) {
                uint32_t t[4];
                ldsm4t(t, bS + kk * 16 * 272 + nq * 32);
                b[2 * nq][0] = t[0]; b[2 * nq][1] = t[1];
                b[2 * nq + 1][0] = t[2]; b[2 * nq + 1][1] = t[3];
            }
#pragma unroll
            for (int mi = 0; mi < 2; ++mi)
#pragma unroll
                for (int ni = 0; ni < 8; ++ni)
                    mma_bf16(acc[mi][ni], a[mi], b[ni]);
        }
        __syncthreads();
    }

    const int gid = lane >> 2, tig2 = (lane & 3) * 2;
#pragma unroll
    for (int mi = 0; mi < 2; ++mi) {
#pragma unroll
        for (int hf = 0; hf < 2; ++hf) {
            int m = by * 128 + wm * 32 + mi * 16 + gid + hf * 8;
            size_t orow_off; const float* rrow = nullptr;
            if (EPI == 2) {
                int win = m / NPOS, npos = m - win * NPOS;
                int b = win >> 6, wy = (win >> 3) & 7, wx = win & 7;
                int py = npos / 7, px = npos - py * 7;
                int yy = wy * 7 + py + 3; if (yy >= 56) yy -= 56;
                int xx = wx * 7 + px + 3; if (xx >= 56) xx -= 56;
                orow_off = ((size_t)b * 3136 + yy * 56 + xx) * (size_t)Nn;
                rrow = res + orow_off;
            } else {
                orow_off = (size_t)m * Nn;
                if (EPI == 3) rrow = res + orow_off;
            }
#pragma unroll
            for (int ni = 0; ni < 8; ++ni) {
                int n = bx * 128 + wn * 64 + ni * 8 + tig2;
                float v0 = acc[mi][ni][hf * 2 + 0] + bias[n];
                float v1 = acc[mi][ni][hf * 2 + 1] + bias[n + 1];
                if (EPI == 1) { v0 = gelu_tanh(v0); v1 = gelu_tanh(v1); }
                if (EPI == 0 || EPI == 1) {
                    *(__nv_bfloat162*)((__nv_bfloat16*)CoutV + orow_off + n) =
                        __floats2bfloat162_rn(v0, v1);
                } else {
                    v0 += rrow[n]; v1 += rrow[n + 1];
                    *(float2*)((float*)CoutV + orow_off + n) = make_float2(v0, v1);
                }
            }
        }
    }
}

// ---------------- launch ----------------------------------------------------------
extern "C" void kernel_launch(void* const* d_in, const int* in_sizes, int n_in,
                              void* d_out, int out_size) {
    const float* x     = (const float*)d_in[0];
    const float* n1s   = (const float*)d_in[1];
    const float* n1b   = (const float*)d_in[2];
    const float* qkvw  = (const float*)d_in[3];
    const float* qkvb  = (const float*)d_in[4];
    const float* projw = (const float*)d_in[5];
    const float* projb = (const float*)d_in[6];
    const float* n2s   = (const float*)d_in[7];
    const float* n2b   = (const float*)d_in[8];
    const float* w1    = (const float*)d_in[9];
    const float* b1    = (const float*)d_in[10];
    const float* w2    = (const float*)d_in[11];
    const float* b2    = (const float*)d_in[12];
    float* out = (float*)d_out;

    __nv_bfloat16 *xw, *qkv, *att, *xn2, *h1, *wqkv, *wproj, *wm1, *wm2;
    float* x2;
    cudaGetSymbolAddress((void**)&xw,   g_xw);
    cudaGetSymbolAddress((void**)&qkv,  g_qkv);
    cudaGetSymbolAddress((void**)&att,  g_att);
    cudaGetSymbolAddress((void**)&x2,   g_x2);
    cudaGetSymbolAddress((void**)&xn2,  g_xn2);
    cudaGetSymbolAddress((void**)&h1,   g_h1);
    cudaGetSymbolAddress((void**)&wqkv, g_wqkv);
    cudaGetSymbolAddress((void**)&wproj,g_wproj);
    cudaGetSymbolAddress((void**)&wm1,  g_wm1);
    cudaGetSymbolAddress((void**)&wm2,  g_wm2);

    static bool attr_done = false;
    if (!attr_done) {
        cudaFuncSetAttribute(hgemm<0>, cudaFuncAttributeMaxDynamicSharedMemorySize, SMEM_GEMM);
        cudaFuncSetAttribute(hgemm<1>, cudaFuncAttributeMaxDynamicSharedMemorySize, SMEM_GEMM);
        cudaFuncSetAttribute(hgemm<2>, cudaFuncAttributeMaxDynamicSharedMemorySize, SMEM_GEMM);
        cudaFuncSetAttribute(hgemm<3>, cudaFuncAttributeMaxDynamicSharedMemorySize, SMEM_GEMM);
        attr_done = true;
    }

    const int wtot = WS0 + WS1 + WS2 + WS3;
    wconv_all<<<(wtot + 255) / 256, 256>>>(qkvw, projw, w1, w2, wqkv, wproj, wm1, wm2);

    ln_kernel<true><<<TOK / 8, 256>>>(x, n1s, n1b, xw);
    hgemm<0><<<dim3(1152 / 128, TOK / 128), 256, SMEM_GEMM>>>(xw, wqkv, qkvb, qkv, nullptr, 1152, CDIM);
    attn_mma<<<NWIN * NHEAD, 32>>>(qkv, att);
    hgemm<2><<<dim3(CDIM / 128, TOK / 128), 256, SMEM_GEMM>>>(att, wproj, projb, x2, x, CDIM, CDIM);
    ln_kernel<false><<<TOK / 8, 256>>>(x2, n2s, n2b, xn2);
    hgemm<1><<<dim3(HID / 128, TOK / 128), 256, SMEM_GEMM>>>(xn2, wm1, b1, h1, nullptr, HID, CDIM);
    hgemm<3><<<dim3(CDIM / 128, TOK / 128), 256, SMEM_GEMM>>>(h1, wm2, b2, out, x2, CDIM, HID);
}

// round 13
// speedup vs baseline: 1.0269x; 1.0269x over previous
#include <cuda_runtime.h>
#include <cuda_bf16.h>
#include <cstdint>
#include <math.h>

#define TOK   200704
#define CDIM  384
#define NHEAD 12
#define DHEAD 32
#define NWIN  4096
#define NPOS  49
#define HID   1536

// ---------------- static scratch ----------------------------------------------
__device__ __nv_bfloat16 g_xw [(size_t)TOK * CDIM];
__device__ __nv_bfloat16 g_qkv[(size_t)TOK * 3 * CDIM];
__device__ __nv_bfloat16 g_att[(size_t)TOK * CDIM];
__device__ float         g_x2 [(size_t)TOK * CDIM];
__device__ __nv_bfloat16 g_xn2[(size_t)TOK * CDIM];
__device__ __nv_bfloat16 g_h1 [(size_t)TOK * HID];
__device__ __nv_bfloat16 g_wqkv [CDIM * 3 * CDIM];
__device__ __nv_bfloat16 g_wproj[CDIM * CDIM];
__device__ __nv_bfloat16 g_wm1  [CDIM * HID];
__device__ __nv_bfloat16 g_wm2  [HID * CDIM];

// ---------------- helpers -------------------------------------------------------
__device__ __forceinline__ uint32_t smem_u32(const void* p) {
    uint32_t a;
    asm("{ .reg .u64 t; cvta.to.shared.u64 t, %1; cvt.u32.u64 %0, t; }" : "=r"(a) : "l"(p));
    return a;
}
__device__ __forceinline__ void cp16(uint32_t dst, const void* src) {
    asm volatile("cp.async.cg.shared.global [%0], [%1], 16;" :: "r"(dst), "l"(src));
}
#define CP_COMMIT() asm volatile("cp.async.commit_group;" ::: "memory")
#define CP_WAIT(n)  asm volatile("cp.async.wait_group %0;" :: "n"(n) : "memory")

__device__ __forceinline__ void ldsm4(uint32_t* r, uint32_t addr) {
    asm volatile("ldmatrix.sync.aligned.m8n8.x4.shared.b16 {%0,%1,%2,%3}, [%4];"
                 : "=r"(r[0]), "=r"(r[1]), "=r"(r[2]), "=r"(r[3]) : "r"(addr));
}
__device__ __forceinline__ void ldsm4t(uint32_t* r, uint32_t addr) {
    asm volatile("ldmatrix.sync.aligned.m8n8.x4.trans.shared.b16 {%0,%1,%2,%3}, [%4];"
                 : "=r"(r[0]), "=r"(r[1]), "=r"(r[2]), "=r"(r[3]) : "r"(addr));
}
__device__ __forceinline__ void mma_bf16(float* c, const uint32_t* a, const uint32_t* b) {
    asm volatile("mma.sync.aligned.m16n8k16.row.col.f32.bf16.bf16.f32 "
                 "{%0,%1,%2,%3}, {%4,%5,%6,%7}, {%8,%9}, {%0,%1,%2,%3};"
                 : "+f"(c[0]), "+f"(c[1]), "+f"(c[2]), "+f"(c[3])
                 : "r"(a[0]), "r"(a[1]), "r"(a[2]), "r"(a[3]), "r"(b[0]), "r"(b[1]));
}
__device__ __forceinline__ uint32_t cvt_bf2(float lo, float hi) {
    uint32_t r;
    asm("cvt.rn.satfinite.bf16x2.f32 %0, %1, %2;" : "=r"(r) : "f"(hi), "f"(lo));
    return r;
}

// ---------------- fused weight convert ------------------------------------------
#define WS0 (CDIM * 3 * CDIM)
#define WS1 (CDIM * CDIM)
#define WS2 (CDIM * HID)
#define WS3 (HID * CDIM)
__global__ void wconv_all(const float* __restrict__ w0, const float* __restrict__ w1,
                          const float* __restrict__ w2, const float* __restrict__ w3,
                          __nv_bfloat16* __restrict__ d0, __nv_bfloat16* __restrict__ d1,
                          __nv_bfloat16* __restrict__ d2, __nv_bfloat16* __restrict__ d3) {
    int i = blockIdx.x * 256 + threadIdx.x;
    if (i < WS0) { d0[i] = __float2bfloat16(w0[i]); return; }
    i -= WS0;
    if (i < WS1) { d1[i] = __float2bfloat16(w1[i]); return; }
    i -= WS1;
    if (i < WS2) { d2[i] = __float2bfloat16(w2[i]); return; }
    i -= WS2;
    if (i < WS3) { d3[i] = __float2bfloat16(w3[i]); }
}

// ---------------- LayerNorm: warp-per-token, float4, shuffle-only reduce --------
template <bool REMAP>
__global__ void __launch_bounds__(256)
ln_kernel(const float* __restrict__ xin,
          const float* __restrict__ sc,
          const float* __restrict__ bi,
          __nv_bfloat16* __restrict__ xout) {
    int t = blockIdx.x * 8 + (threadIdx.x >> 5);
    int lane = threadIdx.x & 31;
    size_t src;
    if (REMAP) {
        int win = t / NPOS, npos = t - win * NPOS;
        int b = win >> 6, wy = (win >> 3) & 7, wx = win & 7;
        int py = npos / 7, px = npos - py * 7;
        int sy = wy * 7 + py + 3; if (sy >= 56) sy -= 56;
        int sx = wx * 7 + px + 3; if (sx >= 56) sx -= 56;
        src = (size_t)b * 3136 + sy * 56 + sx;
    } else src = (size_t)t;

    const float4* xp = (const float4*)(xin + src * CDIM);
    float4 v[3];
    float s = 0.f, s2 = 0.f;
#pragma unroll
    for (int i = 0; i < 3; ++i) {
        v[i] = xp[lane + 32 * i];
        s  += v[i].x + v[i].y + v[i].z + v[i].w;
        s2 += v[i].x * v[i].x + v[i].y * v[i].y + v[i].z * v[i].z + v[i].w * v[i].w;
    }
#pragma unroll
    for (int o = 16; o > 0; o >>= 1) {
        s  += __shfl_xor_sync(0xffffffffu, s,  o);
        s2 += __shfl_xor_sync(0xffffffffu, s2, o);
    }
    float mu  = s * (1.0f / CDIM);
    float var = s2 * (1.0f / CDIM) - mu * mu;
    float r = rsqrtf(var + 1e-6f);

    __nv_bfloat16* op = xout + (size_t)t * CDIM;
#pragma unroll
    for (int i = 0; i < 3; ++i) {
        int idx = (lane + 32 * i) * 4;
        float4 g = *(const float4*)(sc + idx);
        float4 b4 = *(const float4*)(bi + idx);
        float o0 = (v[i].x - mu) * r * g.x + b4.x;
        float o1 = (v[i].y - mu) * r * g.y + b4.y;
        float o2 = (v[i].z - mu) * r * g.z + b4.z;
        float o3 = (v[i].w - mu) * r * g.w + b4.w;
        uint2 pk;
        pk.x = cvt_bf2(o0, o1);
        pk.y = cvt_bf2(o2, o3);
        *(uint2*)(op + idx) = pk;
    }
}

// ---------------- HMMA windowed attention: 2 warps/CTA share K,V smem -----------
// Warp w handles m-tiles {2w, 2w+1}; Q A-frags direct from global; P packed bf16.
__global__ void __launch_bounds__(64)
attn_mma(const __nv_bfloat16* __restrict__ qkv, __nv_bfloat16* __restrict__ out) {
    int blk = blockIdx.x;
    int win = blk / NHEAD, head = blk - win * NHEAD;
    int wy = (win >> 3) & 7, wx = win & 7;

    __shared__ __align__(16) __nv_bfloat16 Ks[64 * 40];
    __shared__ __align__(16) __nv_bfloat16 Vs[64 * 40];
    __shared__ int rg[64];

    const int tid = threadIdx.x;
    const int lane = tid & 31, warp = tid >> 5;
    const __nv_bfloat16* base  = qkv + (size_t)win * NPOS * (3 * CDIM);
    const __nv_bfloat16* qhead = base + head * DHEAD;

    // zero pad rows 49..63 for K and V (64 threads)
#pragma unroll
    for (int i = tid; i < 15 * 20; i += 64) {
        int r = 49 + i / 20, c = i % 20;
        ((float*)Ks)[r * 20 + c] = 0.f;
        ((float*)Vs)[r * 20 + c] = 0.f;
    }
    for (int u = tid; u < 196; u += 64) {
        int r = u >> 2, cc = u & 3;
        const __nv_bfloat16* rp = base + (size_t)r * (3 * CDIM) + head * DHEAD + cc * 8;
        *(uint4*)(Ks + r * 40 + cc * 8) = *(const uint4*)(rp + CDIM);
        *(uint4*)(Vs + r * 40 + cc * 8) = *(const uint4*)(rp + 2 * CDIM);
    }
    for (int p = tid; p < NPOS; p += 64) {
        int py = p / 7, px = p - py * 7;
        int hy = wy * 7 + py, hx = wx * 7 + px;
        int cy = hy < 49 ? 0 : (hy < 53 ? 1 : 2);
        int cx = hx < 49 ? 0 : (hx < 53 ? 1 : 2);
        rg[p] = cy * 3 + cx;
    }
    __syncthreads();

    const uint32_t kb = smem_u32(Ks), vb = smem_u32(Vs);
    const float scale = 0.17677669529663687f;

    int  rk[7][2];
    bool kv_ok[7][2];
#pragma unroll
    for (int nt = 0; nt < 7; ++nt)
#pragma unroll
        for (int c = 0; c < 2; ++c) {
            int k = 8 * nt + 2 * (lane & 3) + c;
            kv_ok[nt][c] = (k < 49);
            rk[nt][c] = rg[k < 49 ? k : 0];
        }

#pragma unroll
    for (int mi = 0; mi < 2; ++mi) {
        int mt = 2 * warp + mi;
        // ---- Q A-frags directly from global (predicated; pad rows -> 0) ----
        int r0 = mt * 16 + (lane >> 2), r1 = r0 + 8;
        bool ok0 = r0 < NPOS, ok1 = r1 < NPOS;
        const __nv_bfloat16* q0p = qhead + (size_t)r0 * (3 * CDIM);
        const __nv_bfloat16* q1p = qhead + (size_t)r1 * (3 * CDIM);
        uint32_t afr[2][4];
#pragma unroll
        for (int kk = 0; kk < 2; ++kk) {
            int c0 = kk * 16 + (lane & 3) * 2, c1 = c0 + 8;
            afr[kk][0] = ok0 ? *(const uint32_t*)(q0p + c0) : 0u;
            afr[kk][1] = ok1 ? *(const uint32_t*)(q1p + c0) : 0u;
            afr[kk][2] = ok0 ? *(const uint32_t*)(q0p + c1) : 0u;
            afr[kk][3] = ok1 ? *(const uint32_t*)(q1p + c1) : 0u;
        }

        float sc[7][4];
#pragma unroll
        for (int nt = 0; nt < 7; ++nt)
#pragma unroll
            for (int r = 0; r < 4; ++r) sc[nt][r] = 0.f;

#pragma unroll
        for (int kk = 0; kk < 2; ++kk) {
#pragma unroll
            for (int np = 0; np < 4; ++np) {
                uint32_t t[4];
                ldsm4(t, kb + (np * 16 + (lane & 15)) * 80 + (lane >> 4) * 16 + kk * 32);
                uint32_t b0[2] = {t[0], t[2]};
                uint32_t b1[2] = {t[1], t[3]};
                mma_bf16(sc[2 * np], afr[kk], b0);
                if (2 * np + 1 < 7) mma_bf16(sc[2 * np + 1], afr[kk], b1);
            }
        }

        // ---- mask + softmax ----
        int rq0 = ok0 ? rg[r0] : -1;
        int rq1 = ok1 ? rg[r1] : -1;
        float mx0 = -1e30f, mx1 = -1e30f;
#pragma unroll
        for (int nt = 0; nt < 7; ++nt) {
#pragma unroll
            for (int r = 0; r < 4; ++r) {
                int half = r >> 1, c = r & 1;
                float s = sc[nt][r] * scale;
                if (!kv_ok[nt][c]) s = -1e30f;
                else if (rk[nt][c] != (half ? rq1 : rq0)) s -= 100.f;
                sc[nt][r] = s;
                if (half == 0) mx0 = fmaxf(mx0, s); else mx1 = fmaxf(mx1, s);
            }
        }
        mx0 = fmaxf(mx0, __shfl_xor_sync(~0u, mx0, 1));
        mx0 = fmaxf(mx0, __shfl_xor_sync(~0u, mx0, 2));
        mx1 = fmaxf(mx1, __shfl_xor_sync(~0u, mx1, 1));
        mx1 = fmaxf(mx1, __shfl_xor_sync(~0u, mx1, 2));
        float s0 = 0.f, s1 = 0.f;
        uint32_t pk[7][2];   // P packed to bf16x2 right away (reg diet)
#pragma unroll
        for (int nt = 0; nt < 7; ++nt) {
            float e0 = __expf(sc[nt][0] - mx0); s0 += e0;
            float e1 = __expf(sc[nt][1] - mx0); s0 += e1;
            float e2 = __expf(sc[nt][2] - mx1); s1 += e2;
            float e3 = __expf(sc[nt][3] - mx1); s1 += e3;
            pk[nt][0] = cvt_bf2(e0, e1);
            pk[nt][1] = cvt_bf2(e2, e3);
        }
        s0 += __shfl_xor_sync(~0u, s0, 1); s0 += __shfl_xor_sync(~0u, s0, 2);
        s1 += __shfl_xor_sync(~0u, s1, 1); s1 += __shfl_xor_sync(~0u, s1, 2);
        float inv0 = 1.f / s0, inv1 = 1.f / s1;

        // ---- O_mt = P_mt V ----
        float acc[4][4];
#pragma unroll
        for (int nt = 0; nt < 4; ++nt)
#pragma unroll
            for (int r = 0; r < 4; ++r) acc[nt][r] = 0.f;

#pragma unroll
        for (int kt = 0; kt < 4; ++kt) {
            uint32_t vbf[4][2];
#pragma unroll
            for (int np = 0; np < 2; ++np) {
                uint32_t t[4];
                ldsm4t(t, vb + (kt * 16 + (lane & 15)) * 80 + ((lane >> 4) * 8 + np * 16) * 2);
                vbf[2 * np][0] = t[0]; vbf[2 * np][1] = t[1];
                vbf[2 * np + 1][0] = t[2]; vbf[2 * np + 1][1] = t[3];
            }
            uint32_t a[4];
            const int ta = 2 * kt, tb = 2 * kt + 1;
            a[0] = pk[ta][0]; a[1] = pk[ta][1];
            if (tb < 7) { a[2] = pk[tb][0]; a[3] = pk[tb][1]; }
            else        { a[2] = 0u;        a[3] = 0u; }
#pragma unroll
            for (int nt = 0; nt < 4; ++nt) mma_bf16(acc[nt], a, vbf[nt]);
        }

#pragma unroll
        for (int half = 0; half < 2; ++half) {
            int q = r0 + 8 * half;
            if (q < NPOS) {
                __nv_bfloat16* op = out + ((size_t)win * NPOS + q) * CDIM + head * DHEAD;
                float iv = half ? inv1 : inv0;
#pragma unroll
                for (int nt = 0; nt < 4; ++nt) {
                    int d = nt * 8 + 2 * (lane & 3);
                    *(__nv_bfloat162*)(op + d) = __floats2bfloat162_rn(
                        acc[nt][2 * half] * iv, acc[nt][2 * half + 1] * iv);
                }
            }
        }
    }
}

// ---------------- HMMA bf16 GEMM (measured-best: 128x128, BK=64, 2 CTA/SM) ------
__device__ __forceinline__ float gelu_tanh(float v) {
    float u = 0.7978845608028654f * (v + 0.044715f * v * v * v);
    return 0.5f * v * (1.0f + tanhf(u));
}

#define ASTG 18432u
#define BSTG 17408u
#define SMEM_GEMM (2u * (ASTG + BSTG))

template <int EPI>
__global__ __launch_bounds__(256, 2)
void hgemm(const __nv_bfloat16* __restrict__ A,
           const __nv_bfloat16* __restrict__ Bw,
           const float* __restrict__ bias,
           void* __restrict__ CoutV,
           const float* __restrict__ res,
           int Nn, int K) {
    extern __shared__ char smraw[];
    const uint32_t a_base = smem_u32(smraw);
    const uint32_t b_base = a_base + 2u * ASTG;

    const int tid = threadIdx.x, lane = tid & 31, warp = tid >> 5;
    const int wm = warp & 3, wn = warp >> 2;
    const int bx = blockIdx.x, by = blockIdx.y;

    const __nv_bfloat16* Ag = A  + (size_t)(by * 128) * K;
    const __nv_bfloat16* Bg = Bw + bx * 128;

    auto load_stage = [&](int buf, int k0) {
        uint32_t a_s = a_base + buf * ASTG;
        uint32_t b_s = b_base + buf * BSTG;
#pragma unroll
        for (int j = 0; j < 4; ++j) {
            int id = tid + j * 256;
            int row = id >> 3, cc = id & 7;
            cp16(a_s + row * 144 + cc * 16, Ag + (size_t)row * K + k0 + cc * 8);
        }
#pragma unroll
        for (int j = 0; j < 4; ++j) {
            int id = tid + j * 256;
            int row = id >> 4, cc = id & 15;
            cp16(b_s + row * 272 + cc * 16, Bg + (size_t)(k0 + row) * Nn + cc * 8);
        }
        CP_COMMIT();
    };

    float acc[2][8][4];
#pragma unroll
    for (int i = 0; i < 2; ++i)
#pragma unroll
        for (int j = 0; j < 8; ++j)
#pragma unroll
            for (int q = 0; q < 4; ++q) acc[i][j][q] = 0.f;

    const int kIters = K >> 6;
    load_stage(0, 0);

    const uint32_t a_lm = a_base + (wm * 32 + (lane & 15)) * 144 + (lane >> 4) * 16;
    const uint32_t b_lm = b_base + (lane & 15) * 272 + (wn * 64 + (lane >> 4) * 8) * 2;

    for (int i = 0; i < kIters; ++i) {
        int cur = i & 1;
        if (i + 1 < kIters) { load_stage(1 - cur, (i + 1) * 64); CP_WAIT(1); }
        else CP_WAIT(0);
        __syncthreads();

        uint32_t aS = a_lm + cur * ASTG;
        uint32_t bS = b_lm + cur * BSTG;
#pragma unroll
        for (int kk = 0; kk < 4; ++kk) {
            uint32_t a[2][4];
#pragma unroll
            for (int mi = 0; mi < 2; ++mi)
                ldsm4(a[mi], aS + mi * 16 * 144 + kk * 32);
            uint32_t b[8][2];
#pragma unroll
            for (int nq = 0; nq < 4; ++nq) {
                uint32_t t[4];
                ldsm4t(t, bS + kk * 16 * 272 + nq * 32);
                b[2 * nq][0] = t[0]; b[2 * nq][1] = t[1];
                b[2 * nq + 1][0] = t[2]; b[2 * nq + 1][1] = t[3];
            }
#pragma unroll
            for (int mi = 0; mi < 2; ++mi)
#pragma unroll
                for (int ni = 0; ni < 8; ++ni)
                    mma_bf16(acc[mi][ni], a[mi], b[ni]);
        }
        __syncthreads();
    }

    const int gid = lane >> 2, tig2 = (lane & 3) * 2;
#pragma unroll
    for (int mi = 0; mi < 2; ++mi) {
#pragma unroll
        for (int hf = 0; hf < 2; ++hf) {
            int m = by * 128 + wm * 32 + mi * 16 + gid + hf * 8;
            size_t orow_off; const float* rrow = nullptr;
            if (EPI == 2) {
                int win = m / NPOS, npos = m - win * NPOS;
                int b = win >> 6, wy = (win >> 3) & 7, wx = win & 7;
                int py = npos / 7, px = npos - py * 7;
                int yy = wy * 7 + py + 3; if (yy >= 56) yy -= 56;
                int xx = wx * 7 + px + 3; if (xx >= 56) xx -= 56;
                orow_off = ((size_t)b * 3136 + yy * 56 + xx) * (size_t)Nn;
                rrow = res + orow_off;
            } else {
                orow_off = (size_t)m * Nn;
                if (EPI == 3) rrow = res + orow_off;
            }
#pragma unroll
            for (int ni = 0; ni < 8; ++ni) {
                int n = bx * 128 + wn * 64 + ni * 8 + tig2;
                float v0 = acc[mi][ni][hf * 2 + 0] + bias[n];
                float v1 = acc[mi][ni][hf * 2 + 1] + bias[n + 1];
                if (EPI == 1) { v0 = gelu_tanh(v0); v1 = gelu_tanh(v1); }
                if (EPI == 0 || EPI == 1) {
                    *(__nv_bfloat162*)((__nv_bfloat16*)CoutV + orow_off + n) =
                        __floats2bfloat162_rn(v0, v1);
                } else {
                    v0 += rrow[n]; v1 += rrow[n + 1];
                    *(float2*)((float*)CoutV + orow_off + n) = make_float2(v0, v1);
                }
            }
        }
    }
}

// ---------------- launch ----------------------------------------------------------
extern "C" void kernel_launch(void* const* d_in, const int* in_sizes, int n_in,
                              void* d_out, int out_size) {
    const float* x     = (const float*)d_in[0];
    const float* n1s   = (const float*)d_in[1];
    const float* n1b   = (const float*)d_in[2];
    const float* qkvw  = (const float*)d_in[3];
    const float* qkvb  = (const float*)d_in[4];
    const float* projw = (const float*)d_in[5];
    const float* projb = (const float*)d_in[6];
    const float* n2s   = (const float*)d_in[7];
    const float* n2b   = (const float*)d_in[8];
    const float* w1    = (const float*)d_in[9];
    const float* b1    = (const float*)d_in[10];
    const float* w2    = (const float*)d_in[11];
    const float* b2    = (const float*)d_in[12];
    float* out = (float*)d_out;

    __nv_bfloat16 *xw, *qkv, *att, *xn2, *h1, *wqkv, *wproj, *wm1, *wm2;
    float* x2;
    cudaGetSymbolAddress((void**)&xw,   g_xw);
    cudaGetSymbolAddress((void**)&qkv,  g_qkv);
    cudaGetSymbolAddress((void**)&att,  g_att);
    cudaGetSymbolAddress((void**)&x2,   g_x2);
    cudaGetSymbolAddress((void**)&xn2,  g_xn2);
    cudaGetSymbolAddress((void**)&h1,   g_h1);
    cudaGetSymbolAddress((void**)&wqkv, g_wqkv);
    cudaGetSymbolAddress((void**)&wproj,g_wproj);
    cudaGetSymbolAddress((void**)&wm1,  g_wm1);
    cudaGetSymbolAddress((void**)&wm2,  g_wm2);

    static bool attr_done = false;
    if (!attr_done) {
        cudaFuncSetAttribute(hgemm<0>, cudaFuncAttributeMaxDynamicSharedMemorySize, SMEM_GEMM);
        cudaFuncSetAttribute(hgemm<1>, cudaFuncAttributeMaxDynamicSharedMemorySize, SMEM_GEMM);
        cudaFuncSetAttribute(hgemm<2>, cudaFuncAttributeMaxDynamicSharedMemorySize, SMEM_GEMM);
        cudaFuncSetAttribute(hgemm<3>, cudaFuncAttributeMaxDynamicSharedMemorySize, SMEM_GEMM);
        attr_done = true;
    }

    const int wtot = WS0 + WS1 + WS2 + WS3;
    wconv_all<<<(wtot + 255) / 256, 256>>>(qkvw, projw, w1, w2, wqkv, wproj, wm1, wm2);

    ln_kernel<true><<<TOK / 8, 256>>>(x, n1s, n1b, xw);
    hgemm<0><<<dim3(1152 / 128, TOK / 128), 256, SMEM_GEMM>>>(xw, wqkv, qkvb, qkv, nullptr, 1152, CDIM);
    attn_mma<<<NWIN * NHEAD, 64>>>(qkv, att);
    hgemm<2><<<dim3(CDIM / 128, TOK / 128), 256, SMEM_GEMM>>>(att, wproj, projb, x2, x, CDIM, CDIM);
    ln_kernel<false><<<TOK / 8, 256>>>(x2, n2s, n2b, xn2);
    hgemm<1><<<dim3(HID / 128, TOK / 128), 256, SMEM_GEMM>>>(xn2, wm1, b1, h1, nullptr, HID, CDIM);
    hgemm<3><<<dim3(CDIM / 128, TOK / 128), 256, SMEM_GEMM>>>(h1, wm2, b2, out, x2, CDIM, HID);
}